// round 17
// baseline (speedup 1.0000x reference)
// Round 17: rope+fp16 fused into QKV-GEMM epilogue (no fp32 q/k/v round-trip),
// reverse-order attention tiles for tail packing. Numerics bit-identical to R16.
#include <cuda_runtime.h>
#include <cuda_fp16.h>
#include <mma.h>
#include <math.h>
#include <cstdint>

using namespace nvcuda;

#define BATCH 2
#define SEQ   2048
#define DIMSZ 4096
#define NH    32
#define NKV   8
#define HD    128
#define MTOK  (BATCH * SEQ)   // 4096 tokens

// ---------------- scratch (static device memory; no allocs allowed) ----------
__device__ __half g_qh[(size_t)MTOK * NH * HD];     // rope(q)*scale, fp16
__device__ __half g_kh[(size_t)MTOK * NKV * HD];    // rope(k), fp16
__device__ __half g_vh[(size_t)MTOK * NKV * HD];    // v, fp16
__device__ __half g_attn_h[(size_t)MTOK * NH * HD];
__device__ __half g_xh[(size_t)MTOK * DIMSZ];
__device__ __half g_wqh[(size_t)DIMSZ * NH * HD];
__device__ __half g_wkh[(size_t)DIMSZ * NKV * HD];
__device__ __half g_wvh[(size_t)DIMSZ * NKV * HD];
__device__ __half g_woh[(size_t)NH * HD * DIMSZ];
__device__ float  g_ctab[SEQ * 64];
__device__ float  g_stab[SEQ * 64];

// ---------------- fp32 -> fp16 conversion, MLP=4 -----------------------------
__global__ void f2h_kernel(const float* __restrict__ in, __half* __restrict__ out,
                           int n4)
{
    int i = blockIdx.x * blockDim.x + threadIdx.x;
    const int stride = gridDim.x * blockDim.x;
    float4 v0, v1, v2, v3;
    int i1 = i + stride, i2 = i + 2 * stride, i3 = i + 3 * stride;
    bool p0 = i < n4, p1 = i1 < n4, p2 = i2 < n4, p3 = i3 < n4;
    if (p0) v0 = ((const float4*)in)[i];
    if (p1) v1 = ((const float4*)in)[i1];
    if (p2) v2 = ((const float4*)in)[i2];
    if (p3) v3 = ((const float4*)in)[i3];
    uint2 o0, o1, o2, o3;
    {
        __half2 a = __floats2half2_rn(v0.x, v0.y), b = __floats2half2_rn(v0.z, v0.w);
        o0.x = *(unsigned*)&a; o0.y = *(unsigned*)&b;
        a = __floats2half2_rn(v1.x, v1.y); b = __floats2half2_rn(v1.z, v1.w);
        o1.x = *(unsigned*)&a; o1.y = *(unsigned*)&b;
        a = __floats2half2_rn(v2.x, v2.y); b = __floats2half2_rn(v2.z, v2.w);
        o2.x = *(unsigned*)&a; o2.y = *(unsigned*)&b;
        a = __floats2half2_rn(v3.x, v3.y); b = __floats2half2_rn(v3.z, v3.w);
        o3.x = *(unsigned*)&a; o3.y = *(unsigned*)&b;
    }
    if (p0) ((uint2*)out)[i]  = o0;
    if (p1) ((uint2*)out)[i1] = o1;
    if (p2) ((uint2*)out)[i2] = o2;
    if (p3) ((uint2*)out)[i3] = o3;
}

// ---------------- cp.async helpers -------------------------------------------
__device__ __forceinline__ void cp_async16h(__half* dst, const __half* src) {
    unsigned s = (unsigned)__cvta_generic_to_shared(dst);
    asm volatile("cp.async.cg.shared.global [%0], [%1], 16;\n" :: "r"(s), "l"(src));
}

// ---------------- fp16-in GEMM mainloop (fills acc fragments) ----------------
#define GA_LD 40
#define GB_LD 136
#define GSTG  (128 * GA_LD + 32 * GB_LD)
#define GEMM_H_SMEM (4 * GSTG * 2)      // 75776 B (also holds 128x132 f32 epi tile)

__device__ __forceinline__ void gemm_h_mainloop(
    const __half* __restrict__ A, const __half* __restrict__ B,
    int Ndim, int Kdim, int bm, int bn, __half* hsm,
    wmma::fragment<wmma::accumulator, 16, 16, 16, float> (&acc)[2][4])
{
    const int tid  = threadIdx.x;

    const int ar = tid >> 2;
    const int ac = (tid & 3) * 8;
    const int br = tid >> 4;
    const int bc = (tid & 15) * 8;

    auto issue = [&](int it) {
        const int k0 = it << 5;
        __half* As = hsm + (it & 3) * GSTG;
        __half* Bs = As + 128 * GA_LD;
        cp_async16h(&As[ar * GA_LD + ac],        &A[(size_t)(bm + ar) * Kdim + k0 + ac]);
        cp_async16h(&As[(ar + 64) * GA_LD + ac], &A[(size_t)(bm + ar + 64) * Kdim + k0 + ac]);
        cp_async16h(&Bs[br * GB_LD + bc],        &B[(size_t)(k0 + br) * Ndim + bn + bc]);
        cp_async16h(&Bs[(br + 16) * GB_LD + bc], &B[(size_t)(k0 + br + 16) * Ndim + bn + bc]);
        asm volatile("cp.async.commit_group;\n" ::: "memory");
    };

    const int warp = tid >> 5;
    const int wr = warp >> 1;
    const int wc = warp & 1;

#pragma unroll
    for (int i = 0; i < 2; i++)
#pragma unroll
        for (int j = 0; j < 4; j++)
            wmma::fill_fragment(acc[i][j], 0.0f);

    const int niter = Kdim >> 5;
    issue(0);
    issue(1);
    issue(2);

    for (int it = 0; it < niter; it++) {
        if (it + 2 < niter) {
            asm volatile("cp.async.wait_group 2;\n" ::: "memory");
        } else if (it + 1 < niter) {
            asm volatile("cp.async.wait_group 1;\n" ::: "memory");
        } else {
            asm volatile("cp.async.wait_group 0;\n" ::: "memory");
        }
        __syncthreads();

        if (it + 3 < niter) issue(it + 3);

        const __half* As = hsm + (it & 3) * GSTG;
        const __half* Bs = As + 128 * GA_LD;

#pragma unroll
        for (int kk = 0; kk < 32; kk += 16) {
            wmma::fragment<wmma::matrix_a, 16, 16, 16, __half, wmma::row_major> af[2];
            wmma::fragment<wmma::matrix_b, 16, 16, 16, __half, wmma::row_major> bf[4];
#pragma unroll
            for (int i = 0; i < 2; i++)
                wmma::load_matrix_sync(af[i], &As[(wr * 32 + i * 16) * GA_LD + kk], GA_LD);
#pragma unroll
            for (int j = 0; j < 4; j++)
                wmma::load_matrix_sync(bf[j], &Bs[kk * GB_LD + wc * 64 + j * 16], GB_LD);
#pragma unroll
            for (int i = 0; i < 2; i++)
#pragma unroll
                for (int j = 0; j < 4; j++)
                    wmma::mma_sync(acc[i][j], af[i], bf[j], acc[i][j]);
        }
    }
}

// Plain GEMM: fp32 global store (output projection)
__global__ __launch_bounds__(256, 2) void gemm_h(
    const __half* __restrict__ A, const __half* __restrict__ B,
    float* __restrict__ C, int Ndim, int Kdim)
{
    extern __shared__ __half hsm[];
    wmma::fragment<wmma::accumulator, 16, 16, 16, float> acc[2][4];
    const int bm = blockIdx.y * 128, bn = blockIdx.x * 128;
    gemm_h_mainloop(A, B, Ndim, Kdim, bm, bn, hsm, acc);

    const int warp = threadIdx.x >> 5;
    const int wr = warp >> 1, wc = warp & 1;
#pragma unroll
    for (int i = 0; i < 2; i++)
#pragma unroll
        for (int j = 0; j < 4; j++)
            wmma::store_matrix_sync(
                &C[(size_t)(bm + wr * 32 + i * 16) * Ndim + bn + wc * 64 + j * 16],
                acc[i][j], Ndim, wmma::mem_row_major);
}

// Fused QKV projection + rope + fp16 store.
// Each 128-wide N-tile is exactly one head; mode 0 = q (rope*scale),
// mode 1 = k (rope), mode 2 = v (convert only).
#define EPI_LD 132
__global__ __launch_bounds__(256, 2) void gemm_h_qkv(
    const __half* __restrict__ xh,
    const __half* __restrict__ wqh, const __half* __restrict__ wkh,
    const __half* __restrict__ wvh,
    __half* __restrict__ qh, __half* __restrict__ kh, __half* __restrict__ vh)
{
    extern __shared__ __half hsm[];
    const int bnTot = blockIdx.x * 128;
    const int bm = blockIdx.y * 128;
    const __half* W;
    __half* Out;
    int Nw, bn, mode, head, nheads;
    if (bnTot < NH * HD) {
        W = wqh; Out = qh; Nw = NH * HD;  bn = bnTot;               mode = 0;
        head = bn / HD; nheads = NH;
    } else if (bnTot < NH * HD + NKV * HD) {
        W = wkh; Out = kh; Nw = NKV * HD; bn = bnTot - NH * HD;     mode = 1;
        head = bn / HD; nheads = NKV;
    } else {
        W = wvh; Out = vh; Nw = NKV * HD; bn = bnTot - (NH + NKV) * HD; mode = 2;
        head = bn / HD; nheads = NKV;
    }

    wmma::fragment<wmma::accumulator, 16, 16, 16, float> acc[2][4];
    gemm_h_mainloop(xh, W, Nw, DIMSZ, bm, bn, hsm, acc);

    // Epilogue: fragments -> smem fp32 tile -> rope/convert -> fp16 gmem.
    float* Tf = (float*)hsm;             // 128 x EPI_LD floats = 67584 B
    __syncthreads();                     // mainloop smem reads complete
    const int warp = threadIdx.x >> 5;
    const int wr = warp >> 1, wc = warp & 1;
#pragma unroll
    for (int i = 0; i < 2; i++)
#pragma unroll
        for (int j = 0; j < 4; j++)
            wmma::store_matrix_sync(
                &Tf[(wr * 32 + i * 16) * EPI_LD + wc * 64 + j * 16],
                acc[i][j], EPI_LD, wmma::mem_row_major);
    __syncthreads();

    const int tid = threadIdx.x;
    const float scl = (mode == 0) ? 0.08838834764831845f : 1.0f;
#pragma unroll
    for (int i = 0; i < 32; i++) {
        int fid = tid + i * 256;         // 8192 pairs
        int r = fid >> 6;
        int p = fid & 63;
        int tok = bm + r;
        float2 ab = *(const float2*)&Tf[r * EPI_LD + 2 * p];
        float ox, oy;
        if (mode < 2) {
            int pos = tok & (SEQ - 1);
            float c = g_ctab[pos * 64 + p];
            float s = g_stab[pos * 64 + p];
            ox = (ab.x * c - ab.y * s) * scl;
            oy = (ab.x * s + ab.y * c) * scl;
        } else {
            ox = ab.x; oy = ab.y;
        }
        __half2 hh = __floats2half2_rn(ox, oy);
        *(__half2*)&Out[((size_t)tok * nheads + head) * HD + 2 * p] = hh;
    }
}

// ---------------- RoPE table --------------------------------------------------
__global__ void rope_table_kernel()
{
    int idx = blockIdx.x * blockDim.x + threadIdx.x;
    if (idx >= SEQ * 64) return;
    int pos = idx >> 6;
    int p = idx & 63;
    double inv = exp(((double)(-2 * p) / 128.0) * log(500000.0));
    float angf = (float)pos * (float)inv;
    double ar = fmod((double)angf, 6.283185307179586476925287);
    float fa = (float)ar;
    g_ctab[idx] = cosf(fa);
    g_stab[idx] = sinf(fa);
}

// ---------------- fp16 WMMA flash attention (fp16 inputs) --------------------
#define AT_LDH 136
#define AT_LDS 72
#define AT_LDO 132
#define OFF_KS  0
#define OFF_VS  (64 * AT_LDH * 2)
#define OFF_SS  (2 * 64 * AT_LDH * 2)
#define OFF_P16 (OFF_SS + 64 * AT_LDS * 4)
#define OFF_PVS (OFF_P16 + 64 * AT_LDS * 2)
#define OFF_STAT (OFF_PVS + 64 * AT_LDO * 4)
#define ATTN_H_SMEM (OFF_STAT + 3 * 64 * 4)

__global__ __launch_bounds__(256, 1) void attn_h_kernel(
    const __half* __restrict__ qh, const __half* __restrict__ kh,
    const __half* __restrict__ vh, __half* __restrict__ o)
{
    extern __shared__ char smraw[];
    __half* Ks  = (__half*)(smraw + OFF_KS);
    __half* Vs  = (__half*)(smraw + OFF_VS);
    float*  Ss  = (float*) (smraw + OFF_SS);
    __half* P16 = (__half*)(smraw + OFF_P16);
    float*  PVs = (float*) (smraw + OFF_PVS);
    float*  rowm   = (float*)(smraw + OFF_STAT);
    float*  rowl   = rowm + 64;
    float*  salpha = rowl + 64;

    const int tid = threadIdx.x;
    const int tx = tid & 15;
    const int ty = tid >> 4;
    const int warp = tid >> 5;
    const int wm = warp >> 1;
    const int wn = warp & 1;
    const int qtile = gridDim.x - 1 - blockIdx.x;   // big tiles launch first
    const int bh = blockIdx.y;
    const int b = bh / NH;
    const int h = bh % NH;
    const int kvh = h / (NH / NKV);

    // Stage Q tile through Ks, capture persistent fragments
#pragma unroll
    for (int i = 0; i < 4; i++) {
        int fid = tid + i * 256;
        int r = fid >> 4;
        int c8 = (fid & 15) * 8;
        int sq = qtile * 64 + r;
        cp_async16h(&Ks[r * AT_LDH + c8],
                    &qh[(((size_t)(b * SEQ + sq)) * NH + h) * HD + c8]);
    }
    asm volatile("cp.async.commit_group;\n" ::: "memory");
    if (tid < 64) { rowm[tid] = -INFINITY; rowl[tid] = 0.0f; }
    asm volatile("cp.async.wait_group 0;\n" ::: "memory");
    __syncthreads();

    wmma::fragment<wmma::matrix_a, 16, 16, 16, __half, wmma::row_major> aq[8];
#pragma unroll
    for (int kk8 = 0; kk8 < 8; kk8++)
        wmma::load_matrix_sync(aq[kk8], &Ks[(wm * 16) * AT_LDH + kk8 * 16], AT_LDH);
    __syncthreads();

    float Oacc[4][8];
#pragma unroll
    for (int i = 0; i < 4; i++)
#pragma unroll
        for (int cc = 0; cc < 8; cc++) Oacc[i][cc] = 0.0f;

    const int prow = tid >> 2;
    const int pq   = tid & 3;

    for (int kt = 0; kt <= qtile; kt++) {
#pragma unroll
        for (int i = 0; i < 4; i++) {
            int fid = tid + i * 256;
            int r = fid >> 4;
            int c8 = (fid & 15) * 8;
            size_t gidx = (((size_t)(b * SEQ + kt * 64 + r)) * NKV + kvh) * HD + c8;
            cp_async16h(&Ks[r * AT_LDH + c8], &kh[gidx]);
            cp_async16h(&Vs[r * AT_LDH + c8], &vh[gidx]);
        }
        asm volatile("cp.async.commit_group;\n" ::: "memory");
        asm volatile("cp.async.wait_group 0;\n" ::: "memory");
        __syncthreads();

        {
            wmma::fragment<wmma::accumulator, 16, 16, 16, float> sfrag[2];
#pragma unroll
            for (int j = 0; j < 2; j++) wmma::fill_fragment(sfrag[j], 0.0f);
#pragma unroll
            for (int kk8 = 0; kk8 < 8; kk8++) {
#pragma unroll
                for (int j = 0; j < 2; j++) {
                    wmma::fragment<wmma::matrix_b, 16, 16, 16, __half, wmma::col_major> bk;
                    wmma::load_matrix_sync(bk, &Ks[(wn * 32 + j * 16) * AT_LDH + kk8 * 16],
                                           AT_LDH);
                    wmma::mma_sync(sfrag[j], aq[kk8], bk, sfrag[j]);
                }
            }
#pragma unroll
            for (int j = 0; j < 2; j++)
                wmma::store_matrix_sync(&Ss[(wm * 16) * AT_LDS + wn * 32 + j * 16],
                                        sfrag[j], AT_LDS, wmma::mem_row_major);
        }
        __syncthreads();

        const bool diag = (kt == qtile);

        {
            const float* sr = &Ss[prow * AT_LDS + pq * 16];
            float mx = -INFINITY;
#pragma unroll
            for (int j = 0; j < 16; j++) {
                int c = pq * 16 + j;
                float sv = sr[j];
                if (!(diag && c > prow)) mx = fmaxf(mx, sv);
            }
            mx = fmaxf(mx, __shfl_xor_sync(0xFFFFFFFFu, mx, 1));
            mx = fmaxf(mx, __shfl_xor_sync(0xFFFFFFFFu, mx, 2));
            float mold = rowm[prow];
            float mnew = fmaxf(mold, mx);
            if (pq == 0) {
                rowm[prow] = mnew;
                salpha[prow] = __expf(mold - mnew);
            }
        }
        __syncthreads();

        {
            const float* sr = &Ss[prow * AT_LDS + pq * 16];
            float m = rowm[prow];
            float ssum = 0.0f;
            __half ph[16];
#pragma unroll
            for (int j = 0; j < 16; j++) {
                int c = pq * 16 + j;
                float p = (diag && c > prow) ? 0.0f : __expf(sr[j] - m);
                ssum += p;
                ph[j] = __float2half_rn(p);
            }
            *(uint4*)&P16[prow * AT_LDS + pq * 16]     = *(uint4*)&ph[0];
            *(uint4*)&P16[prow * AT_LDS + pq * 16 + 8] = *(uint4*)&ph[8];
            ssum += __shfl_xor_sync(0xFFFFFFFFu, ssum, 1);
            ssum += __shfl_xor_sync(0xFFFFFFFFu, ssum, 2);
            if (pq == 0) rowl[prow] = rowl[prow] * salpha[prow] + ssum;
        }
        __syncthreads();

        {
            wmma::fragment<wmma::accumulator, 16, 16, 16, float> ofrag[4];
#pragma unroll
            for (int j = 0; j < 4; j++) wmma::fill_fragment(ofrag[j], 0.0f);
#pragma unroll
            for (int cs = 0; cs < 64; cs += 16) {
                wmma::fragment<wmma::matrix_a, 16, 16, 16, __half, wmma::row_major> ap;
                wmma::load_matrix_sync(ap, &P16[(wm * 16) * AT_LDS + cs], AT_LDS);
#pragma unroll
                for (int j = 0; j < 4; j++) {
                    wmma::fragment<wmma::matrix_b, 16, 16, 16, __half, wmma::row_major> bv;
                    wmma::load_matrix_sync(bv, &Vs[cs * AT_LDH + wn * 64 + j * 16], AT_LDH);
                    wmma::mma_sync(ofrag[j], ap, bv, ofrag[j]);
                }
            }
#pragma unroll
            for (int j = 0; j < 4; j++)
                wmma::store_matrix_sync(&PVs[(wm * 16) * AT_LDO + wn * 64 + j * 16],
                                        ofrag[j], AT_LDO, wmma::mem_row_major);
        }
        __syncthreads();

#pragma unroll
        for (int i = 0; i < 4; i++) {
            int r = ty + 16 * i;
            float a = salpha[r];
            const float* pv = &PVs[r * AT_LDO + tx * 8];
#pragma unroll
            for (int cc = 0; cc < 8; cc++)
                Oacc[i][cc] = Oacc[i][cc] * a + pv[cc];
        }
    }

#pragma unroll
    for (int i = 0; i < 4; i++) {
        int r = ty + 16 * i;
        int sq = qtile * 64 + r;
        float invl = 1.0f / rowl[r];
        __half2 p0 = __floats2half2_rn(Oacc[i][0] * invl, Oacc[i][1] * invl);
        __half2 p1 = __floats2half2_rn(Oacc[i][2] * invl, Oacc[i][3] * invl);
        __half2 p2 = __floats2half2_rn(Oacc[i][4] * invl, Oacc[i][5] * invl);
        __half2 p3 = __floats2half2_rn(Oacc[i][6] * invl, Oacc[i][7] * invl);
        uint4 pk = { *(unsigned*)&p0, *(unsigned*)&p1, *(unsigned*)&p2, *(unsigned*)&p3 };
        *(uint4*)&o[(((size_t)(b * SEQ + sq)) * NH + h) * HD + tx * 8] = pk;
    }
}

// ---------------- launch ------------------------------------------------------
extern "C" void kernel_launch(void* const* d_in, const int* in_sizes, int n_in,
                              void* d_out, int out_size)
{
    const float* x  = (const float*)d_in[0];
    const float* wq = (const float*)d_in[1];
    const float* wk = (const float*)d_in[2];
    const float* wv = (const float*)d_in[3];
    const float* wo = (const float*)d_in[4];
    float* out = (float*)d_out;

    __half* qh2; cudaGetSymbolAddress((void**)&qh2, g_qh);
    __half* kh2; cudaGetSymbolAddress((void**)&kh2, g_kh);
    __half* vh2; cudaGetSymbolAddress((void**)&vh2, g_vh);
    __half* ah;  cudaGetSymbolAddress((void**)&ah,  g_attn_h);
    __half* xh;  cudaGetSymbolAddress((void**)&xh,  g_xh);
    __half* wqh; cudaGetSymbolAddress((void**)&wqh, g_wqh);
    __half* wkh; cudaGetSymbolAddress((void**)&wkh, g_wkh);
    __half* wvh; cudaGetSymbolAddress((void**)&wvh, g_wvh);
    __half* woh; cudaGetSymbolAddress((void**)&woh, g_woh);

    cudaFuncSetAttribute(gemm_h, cudaFuncAttributeMaxDynamicSharedMemorySize,
                         GEMM_H_SMEM);
    cudaFuncSetAttribute(gemm_h_qkv, cudaFuncAttributeMaxDynamicSharedMemorySize,
                         GEMM_H_SMEM);
    cudaFuncSetAttribute(attn_h_kernel, cudaFuncAttributeMaxDynamicSharedMemorySize,
                         ATTN_H_SMEM);

    // fp32 -> fp16 operand conversion
    {
        int n4x = MTOK * DIMSZ / 4;
        int n4q = DIMSZ * NH * HD / 4;
        int n4k = DIMSZ * NKV * HD / 4;
        f2h_kernel<<<(n4x / 4 + 255) / 256, 256>>>(x,  xh,  n4x);
        f2h_kernel<<<(n4q / 4 + 255) / 256, 256>>>(wq, wqh, n4q);
        f2h_kernel<<<(n4k / 4 + 255) / 256, 256>>>(wk, wkh, n4k);
        f2h_kernel<<<(n4k / 4 + 255) / 256, 256>>>(wv, wvh, n4k);
        f2h_kernel<<<(n4q / 4 + 255) / 256, 256>>>(wo, woh, n4q);
    }

    // RoPE table
    rope_table_kernel<<<(SEQ * 64 + 255) / 256, 256>>>();

    // Fused QKV projection + rope + fp16 store
    gemm_h_qkv<<<dim3((NH * HD + 2 * NKV * HD) / 128, MTOK / 128), 256,
                 GEMM_H_SMEM>>>(xh, wqh, wkh, wvh, qh2, kh2, vh2);

    // Flash attention (fp16 in/out)
    attn_h_kernel<<<dim3(SEQ / 64, BATCH * NH), 256, ATTN_H_SMEM>>>(qh2, kh2, vh2, ah);

    // Output projection (fp16 in, fp32 out)
    gemm_h<<<dim3(DIMSZ / 128, MTOK / 128), 256, GEMM_H_SMEM>>>(ah, woh, out, DIMSZ, DIMSZ);
}